// round 14
// baseline (speedup 1.0000x reference)
#include <cuda_runtime.h>
#include <cuda_bf16.h>
#include <math.h>
#include <stdint.h>

// ---------------------------------------------------------------------------
// Problem constants: B=2, S=2048, D=2048, H=16, NOPE=128, ROPE=64, DV=128,
// DQK=192, QLR=1536, KVLR=512, tokens = 4096
// ---------------------------------------------------------------------------
#define TOK 4096
#define SEQ 2048
#define NH 16
#define DQK 192
#define DV 128

// ---------------------------------------------------------------------------
// Device scratch (static, allocation-free)
// ---------------------------------------------------------------------------
__device__ float g_qlat [4096 * 1536];
__device__ float g_kvdr [4096 * 576];
__device__ float g_kvlat[4096 * 512];
__device__ float g_krope[4096 * 64];
__device__ float g_qraw [4096L * 3072];
__device__ float g_kv   [4096L * 4096];
__device__ float g_q    [32L * 2048 * 192];
__device__ float g_k    [32L * 2048 * 192];
__device__ float g_v    [32L * 2048 * 128];
__device__ float g_attn [4096L * 2048];
// tf32-pre-rounded operands for cp.async GEMM path
__device__ float g_hid_t[4096L * 2048];
__device__ float g_w1t  [2048L * 1536];
__device__ float g_w2t  [2048L * 576];
__device__ float g_w3t  [1536L * 3072];
__device__ float g_w4t  [512L  * 4096];
__device__ float g_w5t  [2048L * 2048];

// ---------------------------------------------------------------------------
// helpers
// ---------------------------------------------------------------------------
__device__ __forceinline__ unsigned tf32_rna(float x) {
    unsigned r;
    asm("cvt.rna.tf32.f32 %0, %1;" : "=r"(r) : "f"(x));
    return r;
}
__device__ __forceinline__ float tf32f(float x) {
    return __uint_as_float(tf32_rna(x));
}

__device__ __forceinline__ void mma_tf32(
    float* c, unsigned a0, unsigned a1, unsigned a2, unsigned a3,
    unsigned b0, unsigned b1)
{
    asm volatile(
        "mma.sync.aligned.m16n8k8.row.col.f32.tf32.tf32.f32 "
        "{%0,%1,%2,%3}, {%4,%5,%6,%7}, {%8,%9}, {%0,%1,%2,%3};\n"
        : "+f"(c[0]), "+f"(c[1]), "+f"(c[2]), "+f"(c[3])
        : "r"(a0), "r"(a1), "r"(a2), "r"(a3), "r"(b0), "r"(b1));
}

__device__ __forceinline__ unsigned smem_u32(const void* p) {
    unsigned a;
    asm("{ .reg .u64 t; cvta.to.shared.u64 t, %1; cvt.u32.u64 %0, t; }"
        : "=r"(a) : "l"(p));
    return a;
}

__device__ __forceinline__ void cp_async16(unsigned dst, const void* src) {
    asm volatile("cp.async.ca.shared.global [%0], [%1], 16;\n"
                 :: "r"(dst), "l"(src));
}
__device__ __forceinline__ void cp_async16z(unsigned dst, const void* src, int srcsz) {
    asm volatile("cp.async.ca.shared.global [%0], [%1], 16, %2;\n"
                 :: "r"(dst), "l"(src), "r"(srcsz));
}
__device__ __forceinline__ void cp_commit() {
    asm volatile("cp.async.commit_group;\n");
}
__device__ __forceinline__ void cp_wait1() {
    asm volatile("cp.async.wait_group 1;\n");
}

__device__ __forceinline__ void ldsm_x4(
    unsigned& r0, unsigned& r1, unsigned& r2, unsigned& r3, unsigned addr)
{
    asm volatile("ldmatrix.sync.aligned.m8n8.x4.shared.b16 {%0,%1,%2,%3}, [%4];"
                 : "=r"(r0), "=r"(r1), "=r"(r2), "=r"(r3) : "r"(addr));
}

// ---------------------------------------------------------------------------
// tf32 pre-round convert (inputs must be multiple of 4 elements)
// ---------------------------------------------------------------------------
__global__ __launch_bounds__(256) void cvt_tf32_kernel(
    const float* __restrict__ in, float* __restrict__ out, int n4)
{
    const int i = blockIdx.x * 256 + threadIdx.x;
    if (i < n4) {
        float4 v = ((const float4*)in)[i];
        v.x = tf32f(v.x); v.y = tf32f(v.y);
        v.z = tf32f(v.z); v.w = tf32f(v.w);
        ((float4*)out)[i] = v;
    }
}

// ---------------------------------------------------------------------------
// Pipelined tf32 GEMM: C[M,N] = A[M,K] @ B[K,N], row-major.
// INPUTS MUST BE PRE-ROUNDED TO TF32. 128x128x32 tile, 256 threads,
// 3-stage cp.async pipeline, ldmatrix A-fragments, scalar-LDS B-fragments.
// __launch_bounds__(256, 2): force 2 CTAs/SM (16 warps) to hide LDS/HMMA
// latency. Requires M%128==0, K%32==0 (N guarded).
// ---------------------------------------------------------------------------
#define LDA_S 36
#define LDB_S 136
#define STAGE_A (128 * LDA_S)
#define STAGE_B (32 * LDB_S)
#define STAGE_F (STAGE_A + STAGE_B)
#define NSTAGE 3
#define GEMM_SMEM_BYTES (NSTAGE * STAGE_F * 4)

__global__ __launch_bounds__(256, 2) void gemm_tf32_pipe(
    const float* __restrict__ A, const float* __restrict__ B,
    float* __restrict__ C, int M, int N, int K)
{
    extern __shared__ float sm[];

    const int tid  = threadIdx.x;
    const int lane = tid & 31;
    const int warp = tid >> 5;
    const int g = lane >> 2;
    const int t = lane & 3;
    const int warp_m = (warp & 3) * 32;
    const int warp_n = (warp >> 2) * 64;
    const int row0 = blockIdx.y * 128;
    const int col0 = blockIdx.x * 128;

    // cp.async mappings
    const int ar  = tid >> 3;            // A rows ar + p*32
    const int ac4 = (tid & 7) * 4;       // A col offset within BK
    const int br  = tid >> 5;            // B rows br + p*8
    const int bc4 = (tid & 31) * 4;      // B col within BN
    const int bsz = (col0 + bc4 < N) ? 16 : 0;

    const unsigned smem_u = smem_u32(sm);
    const float* aSrc = A + (size_t)(row0 + ar) * K + ac4;
    const float* bSrc = B + (size_t)br * N + col0 + bc4;
    const unsigned aDst = (unsigned)(ar * LDA_S + ac4) * 4u;
    const unsigned bDst = (unsigned)(STAGE_A + br * LDB_S + bc4) * 4u;

    auto issue = [&](int s, int k0) {
        const unsigned sb = smem_u + (unsigned)(s * STAGE_F) * 4u;
#pragma unroll
        for (int p = 0; p < 4; p++)
            cp_async16(sb + aDst + (unsigned)(p * 32 * LDA_S) * 4u,
                       aSrc + (size_t)p * 32 * K + k0);
#pragma unroll
        for (int p = 0; p < 4; p++)
            cp_async16z(sb + bDst + (unsigned)(p * 8 * LDB_S) * 4u,
                        bSrc + (size_t)(k0 + p * 8) * N, bsz);
        cp_commit();
    };

    // ldmatrix lane addressing for A fragments
    const int lrow = lane & 15;
    const unsigned lcolB = (unsigned)((lane >> 4) << 4);  // 0 or 16 bytes
    const unsigned aBase0 = (unsigned)((warp_m + lrow) * LDA_S) * 4u + lcolB;
    const unsigned aBase1 = (unsigned)((warp_m + 16 + lrow) * LDA_S) * 4u + lcolB;

    float acc[2][8][4];
#pragma unroll
    for (int mt = 0; mt < 2; mt++)
#pragma unroll
        for (int nt = 0; nt < 8; nt++)
#pragma unroll
            for (int i = 0; i < 4; i++) acc[mt][nt][i] = 0.f;

    const int niter = K >> 5;

    issue(0, 0);
    issue(1, 32);
    cp_wait1();
    __syncthreads();

    for (int i = 0; i < niter; i++) {
        const int s = i % NSTAGE;
        if (i + 2 < niter) issue((i + 2) % NSTAGE, (i + 2) * 32);
        else cp_commit();

        const unsigned sA = smem_u + (unsigned)(s * STAGE_F) * 4u;
        const float* Bp = sm + s * STAGE_F + STAGE_A;

#pragma unroll
        for (int kk = 0; kk < 4; kk++) {
            const int kc = kk * 8;
            unsigned a[2][4];
            ldsm_x4(a[0][0], a[0][1], a[0][2], a[0][3], sA + aBase0 + (unsigned)(kc * 4));
            ldsm_x4(a[1][0], a[1][1], a[1][2], a[1][3], sA + aBase1 + (unsigned)(kc * 4));
#pragma unroll
            for (int nt = 0; nt < 8; nt++) {
                const int c = warp_n + nt * 8 + g;
                const unsigned b0 = __float_as_uint(Bp[(kc + t)     * LDB_S + c]);
                const unsigned b1 = __float_as_uint(Bp[(kc + t + 4) * LDB_S + c]);
                mma_tf32(acc[0][nt], a[0][0], a[0][1], a[0][2], a[0][3], b0, b1);
                mma_tf32(acc[1][nt], a[1][0], a[1][1], a[1][2], a[1][3], b0, b1);
            }
        }
        cp_wait1();
        __syncthreads();
    }

    // epilogue
#pragma unroll
    for (int mt = 0; mt < 2; mt++) {
#pragma unroll
        for (int nt = 0; nt < 8; nt++) {
            const int c = col0 + warp_n + nt * 8 + 2 * t;
            if (c < N) {
                const int r = row0 + warp_m + mt * 16 + g;
                float2 v0 = make_float2(acc[mt][nt][0], acc[mt][nt][1]);
                float2 v1 = make_float2(acc[mt][nt][2], acc[mt][nt][3]);
                *(float2*)&C[(size_t)r * N + c] = v0;
                *(float2*)&C[(size_t)(r + 8) * N + c] = v1;
            }
        }
    }
}

// ---------------------------------------------------------------------------
// Block reduction & elementwise kernels
// ---------------------------------------------------------------------------
__device__ __forceinline__ float block_reduce_sum_256(float v) {
    __shared__ float red[8];
    __shared__ float result;
    const int lane = threadIdx.x & 31;
    const int w = threadIdx.x >> 5;
#pragma unroll
    for (int o = 16; o > 0; o >>= 1)
        v += __shfl_xor_sync(0xffffffffu, v, o);
    if (lane == 0) red[w] = v;
    __syncthreads();
    if (threadIdx.x == 0) {
        float s = 0.f;
#pragma unroll
        for (int i = 0; i < 8; i++) s += red[i];
        result = s;
    }
    __syncthreads();
    return result;
}

// rmsnorm, output tf32-rounded (feeds a GEMM directly)
__global__ __launch_bounds__(256) void rmsnorm_kernel(float* __restrict__ data, int L) {
    const size_t base = (size_t)blockIdx.x * L;
    float ss = 0.f;
    for (int i = threadIdx.x; i < L; i += 256) {
        float x = data[base + i];
        ss += x * x;
    }
    const float tot = block_reduce_sum_256(ss);
    const float r = rsqrtf(tot / (float)L + 1e-5f);
    for (int i = threadIdx.x; i < L; i += 256)
        data[base + i] = tf32f(data[base + i] * r);
}

__global__ __launch_bounds__(256) void kvprep_kernel(
    const float* __restrict__ kvdr, const float* __restrict__ cosb,
    const float* __restrict__ sinb, float* __restrict__ kvlat,
    float* __restrict__ krope)
{
    const int t = blockIdx.x;
    const int s = t & (SEQ - 1);
    const float* row = kvdr + (size_t)t * 576;

    float ss = 0.f;
    for (int i = threadIdx.x; i < 512; i += 256) {
        float x = row[i];
        ss += x * x;
    }
    const float tot = block_reduce_sum_256(ss);
    const float r = rsqrtf(tot / 512.f + 1e-5f);
    for (int i = threadIdx.x; i < 512; i += 256)
        kvlat[(size_t)t * 512 + i] = tf32f(row[i] * r);

    if (threadIdx.x < 32) {
        const int i = threadIdx.x;
        const float x0 = row[512 + 2 * i];
        const float x1 = row[512 + 2 * i + 1];
        const float c  = cosb[s * 32 + i];
        const float sn = sinb[s * 32 + i];
        krope[(size_t)t * 64 + 2 * i]     = x0 * c - x1 * sn;
        krope[(size_t)t * 64 + 2 * i + 1] = x0 * sn + x1 * c;
    }
}

__global__ __launch_bounds__(256) void buildq_kernel(
    const float* __restrict__ qraw, const float* __restrict__ cosb,
    const float* __restrict__ sinb, float* __restrict__ gq)
{
    const int t = blockIdx.x;
    const int b = t >> 11;
    const int s = t & (SEQ - 1);
    const float* row = qraw + (size_t)t * 3072;

    for (int u = threadIdx.x; u < 512; u += 256) {
        const int h = u >> 5;
        const int p = u & 31;
        const float x0 = row[h * 192 + 128 + 2 * p];
        const float x1 = row[h * 192 + 128 + 2 * p + 1];
        const float c  = cosb[s * 32 + p];
        const float sn = sinb[s * 32 + p];
        const size_t o = ((size_t)(b * NH + h) * SEQ + s) * DQK;
        gq[o + 2 * p]     = x0 * c - x1 * sn;
        gq[o + 2 * p + 1] = x0 * sn + x1 * c;
    }
    for (int u = threadIdx.x; u < 2048; u += 256) {
        const int h = u >> 7;
        const int j = u & 127;
        const size_t o = ((size_t)(b * NH + h) * SEQ + s) * DQK;
        gq[o + 64 + j] = row[h * 192 + j];
    }
}

__global__ __launch_bounds__(256) void buildkv_kernel(
    const float* __restrict__ kv, const float* __restrict__ krope,
    float* __restrict__ gk, float* __restrict__ gv)
{
    const int t = blockIdx.x;
    const int b = t >> 11;
    const int s = t & (SEQ - 1);
    const float* kvrow = kv + (size_t)t * 4096;
    const float* krow = krope + (size_t)t * 64;

    for (int u = threadIdx.x; u < NH * DQK; u += 256) {
        const int h = u / DQK;
        const int d = u % DQK;
        const size_t o = ((size_t)(b * NH + h) * SEQ + s) * DQK;
        gk[o + d] = (d < 64) ? krow[d] : kvrow[h * 128 + (d - 64)];
    }
    for (int u = threadIdx.x; u < NH * DV; u += 256) {
        const int h = u >> 7;
        const int j = u & 127;
        const size_t o = ((size_t)(b * NH + h) * SEQ + s) * DV;
        gv[o + j] = kvrow[2048 + h * 128 + j];
    }
}

// ---------------------------------------------------------------------------
// Tensor-core flash attention (causal). BQ=BK=64, 256 threads (8 warps, 4x2).
// Output tf32-rounded (feeds the Wo GEMM).
// ---------------------------------------------------------------------------
#define AQ_S 196
#define AV_S 136
#define AS_S 68
#define ATTN_SMEM_FLOATS (2 * 64 * AQ_S + 64 * AV_S + 64 * AS_S + 3 * 64)
#define ATTN_SMEM_BYTES (ATTN_SMEM_FLOATS * 4)

__global__ __launch_bounds__(256) void attn_tc_kernel(
    const float* __restrict__ gq, const float* __restrict__ gk,
    const float* __restrict__ gv, float* __restrict__ gout)
{
    extern __shared__ float sm[];
    unsigned* Qs = (unsigned*)sm;
    unsigned* Ks = Qs + 64 * AQ_S;
    unsigned* Vs = Ks + 64 * AQ_S;
    float* Ss    = (float*)(Vs + 64 * AV_S);
    float* mrow  = Ss + 64 * AS_S;
    float* lrow  = mrow + 64;
    float* frow  = lrow + 64;

    const int tid  = threadIdx.x;
    const int lane = tid & 31;
    const int warp = tid >> 5;
    const int g = lane >> 2;
    const int t = lane & 3;
    const int warp_m  = (warp & 3) * 16;
    const int warp_nS = (warp >> 2) * 32;
    const int warp_nO = (warp >> 2) * 64;
    const int qt = blockIdx.x;
    const int bh = blockIdx.y;
    const int q0 = qt * 64;
    const float scale = 0.07216878364870323f;

    const size_t qk_base = (size_t)bh * SEQ * DQK;
    const size_t v_base  = (size_t)bh * SEQ * DV;

    for (int u = tid; u < 64 * 48; u += 256) {
        const int r = u / 48;
        const int c4 = (u % 48) * 4;
        const float4 v = *(const float4*)&gq[qk_base + (size_t)(q0 + r) * DQK + c4];
        Qs[r * AQ_S + c4 + 0] = tf32_rna(v.x);
        Qs[r * AQ_S + c4 + 1] = tf32_rna(v.y);
        Qs[r * AQ_S + c4 + 2] = tf32_rna(v.z);
        Qs[r * AQ_S + c4 + 3] = tf32_rna(v.w);
    }
    if (tid < 64) { mrow[tid] = -1e30f; lrow[tid] = 0.f; }

    float oacc[8][4];
#pragma unroll
    for (int nt = 0; nt < 8; nt++)
#pragma unroll
        for (int i = 0; i < 4; i++) oacc[nt][i] = 0.f;

    __syncthreads();

    for (int kt = 0; kt <= qt; kt++) {
        const int k0 = kt * 64;

        for (int u = tid; u < 64 * 48; u += 256) {
            const int r = u / 48;
            const int c4 = (u % 48) * 4;
            const float4 v = *(const float4*)&gk[qk_base + (size_t)(k0 + r) * DQK + c4];
            Ks[r * AQ_S + c4 + 0] = tf32_rna(v.x);
            Ks[r * AQ_S + c4 + 1] = tf32_rna(v.y);
            Ks[r * AQ_S + c4 + 2] = tf32_rna(v.z);
            Ks[r * AQ_S + c4 + 3] = tf32_rna(v.w);
        }
        for (int u = tid; u < 64 * 32; u += 256) {
            const int r = u >> 5;
            const int c4 = (u & 31) << 2;
            const float4 v = *(const float4*)&gv[v_base + (size_t)(k0 + r) * DV + c4];
            Vs[r * AV_S + c4 + 0] = tf32_rna(v.x);
            Vs[r * AV_S + c4 + 1] = tf32_rna(v.y);
            Vs[r * AV_S + c4 + 2] = tf32_rna(v.z);
            Vs[r * AV_S + c4 + 3] = tf32_rna(v.w);
        }
        __syncthreads();

        float sacc[4][4];
#pragma unroll
        for (int nt = 0; nt < 4; nt++)
#pragma unroll
            for (int i = 0; i < 4; i++) sacc[nt][i] = 0.f;

#pragma unroll
        for (int ks = 0; ks < 24; ks++) {
            const int kc = ks * 8;
            const unsigned a0 = Qs[(warp_m + g)     * AQ_S + kc + t];
            const unsigned a1 = Qs[(warp_m + g + 8) * AQ_S + kc + t];
            const unsigned a2 = Qs[(warp_m + g)     * AQ_S + kc + t + 4];
            const unsigned a3 = Qs[(warp_m + g + 8) * AQ_S + kc + t + 4];
#pragma unroll
            for (int nt = 0; nt < 4; nt++) {
                const int n = warp_nS + nt * 8 + g;
                const unsigned b0 = Ks[n * AQ_S + kc + t];
                const unsigned b1 = Ks[n * AQ_S + kc + t + 4];
                mma_tf32(sacc[nt], a0, a1, a2, a3, b0, b1);
            }
        }

        const bool diag = (kt == qt);
#pragma unroll
        for (int nt = 0; nt < 4; nt++) {
            const int col = warp_nS + nt * 8 + 2 * t;
            const int r0 = warp_m + g;
            const int r1 = r0 + 8;
            float s00 = sacc[nt][0] * scale, s01 = sacc[nt][1] * scale;
            float s10 = sacc[nt][2] * scale, s11 = sacc[nt][3] * scale;
            if (diag) {
                const int gi0 = q0 + r0, gi1 = q0 + r1;
                const int gj0 = k0 + col, gj1 = gj0 + 1;
                if (gj0 > gi0) s00 = -1e9f;
                if (gj1 > gi0) s01 = -1e9f;
                if (gj0 > gi1) s10 = -1e9f;
                if (gj1 > gi1) s11 = -1e9f;
            }
            *(float2*)&Ss[r0 * AS_S + col] = make_float2(s00, s01);
            *(float2*)&Ss[r1 * AS_S + col] = make_float2(s10, s11);
        }
        __syncthreads();

#pragma unroll
        for (int rr = 0; rr < 8; rr++) {
            const int i = warp * 8 + rr;
            const float x0 = Ss[i * AS_S + lane];
            const float x1 = Ss[i * AS_S + lane + 32];
            float mx = fmaxf(x0, x1);
#pragma unroll
            for (int o = 16; o > 0; o >>= 1)
                mx = fmaxf(mx, __shfl_xor_sync(0xffffffffu, mx, o));
            const float mold = mrow[i];
            const float mnew = fmaxf(mold, mx);
            const float p0 = __expf(x0 - mnew);
            const float p1 = __expf(x1 - mnew);
            float s = p0 + p1;
#pragma unroll
            for (int o = 16; o > 0; o >>= 1)
                s += __shfl_xor_sync(0xffffffffu, s, o);
            ((unsigned*)Ss)[i * AS_S + lane]      = tf32_rna(p0);
            ((unsigned*)Ss)[i * AS_S + lane + 32] = tf32_rna(p1);
            if (lane == 0) {
                const float f = __expf(mold - mnew);
                lrow[i] = lrow[i] * f + s;
                mrow[i] = mnew;
                frow[i] = f;
            }
        }
        __syncthreads();

        const float f0 = frow[warp_m + g];
        const float f1 = frow[warp_m + g + 8];
#pragma unroll
        for (int nt = 0; nt < 8; nt++) {
            oacc[nt][0] *= f0; oacc[nt][1] *= f0;
            oacc[nt][2] *= f1; oacc[nt][3] *= f1;
        }
        const unsigned* Psu = (const unsigned*)Ss;
#pragma unroll
        for (int ks = 0; ks < 8; ks++) {
            const int kc = ks * 8;
            const unsigned a0 = Psu[(warp_m + g)     * AS_S + kc + t];
            const unsigned a1 = Psu[(warp_m + g + 8) * AS_S + kc + t];
            const unsigned a2 = Psu[(warp_m + g)     * AS_S + kc + t + 4];
            const unsigned a3 = Psu[(warp_m + g + 8) * AS_S + kc + t + 4];
#pragma unroll
            for (int nt = 0; nt < 8; nt++) {
                const int col = warp_nO + nt * 8 + g;
                const unsigned b0 = Vs[(kc + t)     * AV_S + col];
                const unsigned b1 = Vs[(kc + t + 4) * AV_S + col];
                mma_tf32(oacc[nt], a0, a1, a2, a3, b0, b1);
            }
        }
        __syncthreads();
    }

    const int b = bh >> 4;
    const int h = bh & 15;
    const float inv0 = 1.0f / lrow[warp_m + g];
    const float inv1 = 1.0f / lrow[warp_m + g + 8];
    const size_t row0 = (size_t)(b * SEQ + q0 + warp_m + g) * 2048 + h * DV;
    const size_t row1 = row0 + 8 * 2048;
#pragma unroll
    for (int nt = 0; nt < 8; nt++) {
        const int col = warp_nO + nt * 8 + 2 * t;
        *(float2*)&gout[row0 + col] =
            make_float2(tf32f(oacc[nt][0] * inv0), tf32f(oacc[nt][1] * inv0));
        *(float2*)&gout[row1 + col] =
            make_float2(tf32f(oacc[nt][2] * inv1), tf32f(oacc[nt][3] * inv1));
    }
}

// ---------------------------------------------------------------------------
// launch
// ---------------------------------------------------------------------------
extern "C" void kernel_launch(void* const* d_in, const int* in_sizes, int n_in,
                              void* d_out, int out_size)
{
    const float* hidden   = (const float*)d_in[0];
    const float* cosb     = (const float*)d_in[2];
    const float* sinb     = (const float*)d_in[3];
    const float* Wq_down  = (const float*)d_in[4];
    const float* Wkv_down = (const float*)d_in[5];
    const float* Wq_up    = (const float*)d_in[6];
    const float* Wkv_up   = (const float*)d_in[7];
    const float* Wo       = (const float*)d_in[8];
    float* out = (float*)d_out;

    float *qlat, *kvdr, *kvlat, *krope, *qraw, *kv, *q, *k, *v, *attn;
    float *hidt, *w1t, *w2t, *w3t, *w4t, *w5t;
    cudaGetSymbolAddress((void**)&qlat,  g_qlat);
    cudaGetSymbolAddress((void**)&kvdr,  g_kvdr);
    cudaGetSymbolAddress((void**)&kvlat, g_kvlat);
    cudaGetSymbolAddress((void**)&krope, g_krope);
    cudaGetSymbolAddress((void**)&qraw,  g_qraw);
    cudaGetSymbolAddress((void**)&kv,    g_kv);
    cudaGetSymbolAddress((void**)&q,     g_q);
    cudaGetSymbolAddress((void**)&k,     g_k);
    cudaGetSymbolAddress((void**)&v,     g_v);
    cudaGetSymbolAddress((void**)&attn,  g_attn);
    cudaGetSymbolAddress((void**)&hidt,  g_hid_t);
    cudaGetSymbolAddress((void**)&w1t,   g_w1t);
    cudaGetSymbolAddress((void**)&w2t,   g_w2t);
    cudaGetSymbolAddress((void**)&w3t,   g_w3t);
    cudaGetSymbolAddress((void**)&w4t,   g_w4t);
    cudaGetSymbolAddress((void**)&w5t,   g_w5t);

    cudaFuncSetAttribute(attn_tc_kernel,
                         cudaFuncAttributeMaxDynamicSharedMemorySize,
                         ATTN_SMEM_BYTES);
    cudaFuncSetAttribute(gemm_tf32_pipe,
                         cudaFuncAttributeMaxDynamicSharedMemorySize,
                         GEMM_SMEM_BYTES);

    // 0. pre-round GEMM operands to tf32
    cvt_tf32_kernel<<<(4096 * 2048 / 4 + 255) / 256, 256>>>(hidden,   hidt, 4096 * 2048 / 4);
    cvt_tf32_kernel<<<(2048 * 1536 / 4 + 255) / 256, 256>>>(Wq_down,  w1t,  2048 * 1536 / 4);
    cvt_tf32_kernel<<<(2048 * 576  / 4 + 255) / 256, 256>>>(Wkv_down, w2t,  2048 * 576  / 4);
    cvt_tf32_kernel<<<(1536 * 3072 / 4 + 255) / 256, 256>>>(Wq_up,    w3t,  1536 * 3072 / 4);
    cvt_tf32_kernel<<<(512  * 4096 / 4 + 255) / 256, 256>>>(Wkv_up,   w4t,  512  * 4096 / 4);
    cvt_tf32_kernel<<<(2048 * 2048 / 4 + 255) / 256, 256>>>(Wo,       w5t,  2048 * 2048 / 4);

    // 1. q latent = hidden @ Wq_down
    gemm_tf32_pipe<<<dim3(12, 32), 256, GEMM_SMEM_BYTES>>>(hidt, w1t, qlat, TOK, 1536, 2048);
    // 2. kvdr = hidden @ Wkv_down
    gemm_tf32_pipe<<<dim3(5, 32), 256, GEMM_SMEM_BYTES>>>(hidt, w2t, kvdr, TOK, 576, 2048);
    // 3. rmsnorm q latent (rounds output)
    rmsnorm_kernel<<<TOK, 256>>>(qlat, 1536);
    // 4. kv latent rmsnorm + k_rope rope (rounds kvlat)
    kvprep_kernel<<<TOK, 256>>>(kvdr, cosb, sinb, kvlat, krope);
    // 5. q raw = qlat @ Wq_up
    gemm_tf32_pipe<<<dim3(24, 32), 256, GEMM_SMEM_BYTES>>>(qlat, w3t, qraw, TOK, 3072, 1536);
    // 6. kv = kvlat @ Wkv_up
    gemm_tf32_pipe<<<dim3(32, 32), 256, GEMM_SMEM_BYTES>>>(kvlat, w4t, kv, TOK, 4096, 512);
    // 7. build q
    buildq_kernel<<<TOK, 256>>>(qraw, cosb, sinb, q);
    // 8. build k, v
    buildkv_kernel<<<TOK, 256>>>(kv, krope, k, v);
    // 9. tensor-core flash attention (rounds output)
    attn_tc_kernel<<<dim3(SEQ / 64, 2 * NH), 256, ATTN_SMEM_BYTES>>>(q, k, v, attn);
    // 10. out = attn @ Wo
    gemm_tf32_pipe<<<dim3(16, 32), 256, GEMM_SMEM_BYTES>>>(attn, w5t, out, TOK, 2048, 2048);
}

// round 16
// speedup vs baseline: 1.2367x; 1.2367x over previous
#include <cuda_runtime.h>
#include <cuda_fp16.h>
#include <math.h>
#include <stdint.h>

// ---------------------------------------------------------------------------
// Problem constants: B=2, S=2048, D=2048, H=16, NOPE=128, ROPE=64, DV=128,
// DQK=192, QLR=1536, KVLR=512, tokens = 4096
// ---------------------------------------------------------------------------
#define TOK 4096
#define SEQ 2048
#define NH 16
#define DQK 192
#define DV 128

// ---------------------------------------------------------------------------
// Device scratch (static, allocation-free)
// ---------------------------------------------------------------------------
__device__ float  g_qlat [4096 * 1536];          // GEMM1 out (fp32)
__device__ float  g_kvdr [4096 * 576];           // GEMM2 out
__device__ float  g_krope[4096 * 64];
__device__ float  g_qraw [4096L * 3072];         // GEMM3 out
__device__ float  g_kv   [4096L * 4096];         // GEMM4 out
__device__ float  g_q    [32L * 2048 * 192];
__device__ float  g_k    [32L * 2048 * 192];
__device__ float  g_v    [32L * 2048 * 128];
// fp16 GEMM operands
__device__ __half g_hid_h [4096L * 2048];        // A for GEMM1/2
__device__ __half g_qlat_h[4096L * 1536];        // A for GEMM3 (rmsnormed)
__device__ __half g_kvlat_h[4096L * 512];        // A for GEMM4 (rmsnormed)
__device__ __half g_attn_h[4096L * 2048];        // A for GEMM5
__device__ __half g_w1h [1536L * 2048];          // Bt = W^T [N][K]
__device__ __half g_w2h [576L  * 2048];
__device__ __half g_w3h [3072L * 1536];
__device__ __half g_w4h [4096L * 512];
__device__ __half g_w5h [2048L * 2048];

// ---------------------------------------------------------------------------
// helpers
// ---------------------------------------------------------------------------
__device__ __forceinline__ unsigned tf32_rna(float x) {
    unsigned r;
    asm("cvt.rna.tf32.f32 %0, %1;" : "=r"(r) : "f"(x));
    return r;
}

__device__ __forceinline__ void mma_tf32(
    float* c, unsigned a0, unsigned a1, unsigned a2, unsigned a3,
    unsigned b0, unsigned b1)
{
    asm volatile(
        "mma.sync.aligned.m16n8k8.row.col.f32.tf32.tf32.f32 "
        "{%0,%1,%2,%3}, {%4,%5,%6,%7}, {%8,%9}, {%0,%1,%2,%3};\n"
        : "+f"(c[0]), "+f"(c[1]), "+f"(c[2]), "+f"(c[3])
        : "r"(a0), "r"(a1), "r"(a2), "r"(a3), "r"(b0), "r"(b1));
}

__device__ __forceinline__ void mma_f16(
    float* c, unsigned a0, unsigned a1, unsigned a2, unsigned a3,
    unsigned b0, unsigned b1)
{
    asm volatile(
        "mma.sync.aligned.m16n8k16.row.col.f32.f16.f16.f32 "
        "{%0,%1,%2,%3}, {%4,%5,%6,%7}, {%8,%9}, {%0,%1,%2,%3};\n"
        : "+f"(c[0]), "+f"(c[1]), "+f"(c[2]), "+f"(c[3])
        : "r"(a0), "r"(a1), "r"(a2), "r"(a3), "r"(b0), "r"(b1));
}

__device__ __forceinline__ unsigned smem_u32(const void* p) {
    unsigned a;
    asm("{ .reg .u64 t; cvta.to.shared.u64 t, %1; cvt.u32.u64 %0, t; }"
        : "=r"(a) : "l"(p));
    return a;
}
__device__ __forceinline__ void cp_async16(unsigned dst, const void* src) {
    asm volatile("cp.async.ca.shared.global [%0], [%1], 16;\n" :: "r"(dst), "l"(src));
}
__device__ __forceinline__ void cp_async16z(unsigned dst, const void* src, int srcsz) {
    asm volatile("cp.async.ca.shared.global [%0], [%1], 16, %2;\n"
                 :: "r"(dst), "l"(src), "r"(srcsz));
}
__device__ __forceinline__ void cp_commit() {
    asm volatile("cp.async.commit_group;\n");
}
__device__ __forceinline__ void cp_wait1() {
    asm volatile("cp.async.wait_group 1;\n");
}
__device__ __forceinline__ void ldsm_x4(
    unsigned& r0, unsigned& r1, unsigned& r2, unsigned& r3, unsigned addr)
{
    asm volatile("ldmatrix.sync.aligned.m8n8.x4.shared.b16 {%0,%1,%2,%3}, [%4];"
                 : "=r"(r0), "=r"(r1), "=r"(r2), "=r"(r3) : "r"(addr));
}

// ---------------------------------------------------------------------------
// fp32 -> fp16 convert (n4 = element count / 4)
// ---------------------------------------------------------------------------
__global__ __launch_bounds__(256) void cvt_f16_kernel(
    const float* __restrict__ in, __half* __restrict__ out, int n4)
{
    const int i = blockIdx.x * 256 + threadIdx.x;
    if (i < n4) {
        const float4 v = ((const float4*)in)[i];
        __half2* o = (__half2*)(out + (size_t)i * 4);
        o[0] = __floats2half2_rn(v.x, v.y);
        o[1] = __floats2half2_rn(v.z, v.w);
    }
}

// ---------------------------------------------------------------------------
// Weight transpose + fp16: in[K][N] fp32 -> out[N][K] half. K,N % 32 == 0.
// ---------------------------------------------------------------------------
__global__ __launch_bounds__(256) void wtrans_h_kernel(
    const float* __restrict__ in, __half* __restrict__ out, int K, int N)
{
    __shared__ float ts[32][33];
    const int n0 = blockIdx.x * 32;
    const int k0 = blockIdx.y * 32;
    const int tx = threadIdx.x & 31;
    const int ty = threadIdx.x >> 5;
#pragma unroll
    for (int p = 0; p < 4; p++)
        ts[ty + p * 8][tx] = in[(size_t)(k0 + ty + p * 8) * N + n0 + tx];
    __syncthreads();
#pragma unroll
    for (int p = 0; p < 4; p++)
        out[(size_t)(n0 + ty + p * 8) * K + k0 + tx] =
            __float2half_rn(ts[tx][ty + p * 8]);
}

// ---------------------------------------------------------------------------
// fp16 tensor-core GEMM: C[M,N] = A[M,K] @ Bt[N,K]^T, fp32 accum/output.
// 128x128x32 tile, 256 threads (8 warps 4x2, warp 32x64), 3-stage cp.async,
// ldmatrix fragments for both A and B. Smem rows 64B payload @ 80B stride
// (start bank 20r mod 32 -> all LDSM phases conflict-free).
// M%128==0, K%32==0; N guarded.
// ---------------------------------------------------------------------------
#define HLD 80
#define HSTAGE_BYTES (2 * 128 * HLD)    // A region + B region = 20480
#define NSTAGE 3
#define GEMM_SMEM_BYTES (NSTAGE * HSTAGE_BYTES)  // 61440

__global__ __launch_bounds__(256) void gemm_f16_pipe(
    const __half* __restrict__ A, const __half* __restrict__ Bt,
    float* __restrict__ C, int M, int N, int K)
{
    extern __shared__ char smc[];
    const unsigned smem_u = smem_u32(smc);

    const int tid  = threadIdx.x;
    const int lane = tid & 31;
    const int warp = tid >> 5;
    const int g = lane >> 2;
    const int t = lane & 3;
    const int warp_m = (warp & 3) * 32;
    const int warp_n = (warp >> 2) * 64;
    const int row0 = blockIdx.y * 128;
    const int col0 = blockIdx.x * 128;

    // cp.async mapping: thread -> (row, 32B half of the 64B row payload)
    const int lrow  = tid >> 1;                 // 0..127
    const int lhalf = tid & 1;                  // 0/1
    const __half* aSrc = A  + (size_t)(row0 + lrow) * K + lhalf * 16;
    const __half* bSrc = Bt + (size_t)(col0 + lrow) * K + lhalf * 16;
    const int bok = (col0 + lrow < N) ? 16 : 0;
    const unsigned aDst = (unsigned)(lrow * HLD + lhalf * 32);
    const unsigned bDst = (unsigned)(128 * HLD + lrow * HLD + lhalf * 32);

    auto issue = [&](int s, int k0) {
        const unsigned sb = smem_u + (unsigned)s * HSTAGE_BYTES;
        cp_async16(sb + aDst,      aSrc + k0);
        cp_async16(sb + aDst + 16, aSrc + k0 + 8);
        cp_async16z(sb + bDst,      bSrc + k0,     bok);
        cp_async16z(sb + bDst + 16, bSrc + k0 + 8, bok);
        cp_commit();
    };

    // ldmatrix lane addressing
    // A (x4): lanes 0-7 rows m+0..7 off0 | 8-15 rows m+8..15 off0 |
    //         16-23 rows m+0..7 off16 | 24-31 rows m+8..15 off16
    const unsigned aFr = (unsigned)((warp_m + (lane & 15)) * HLD + ((lane >> 4) << 4));
    // B (x4): lanes 0-7 rows n+0..7 off0 | 8-15 rows n+0..7 off16 |
    //         16-23 rows n+8..15 off0 | 24-31 rows n+8..15 off16
    const unsigned bFr = (unsigned)(128 * HLD +
        (warp_n + (lane & 7) + ((lane & 16) >> 1)) * HLD + ((lane & 8) << 1));

    float acc[2][8][4];
#pragma unroll
    for (int mt = 0; mt < 2; mt++)
#pragma unroll
        for (int nt = 0; nt < 8; nt++)
#pragma unroll
            for (int i = 0; i < 4; i++) acc[mt][nt][i] = 0.f;

    const int niter = K >> 5;

    issue(0, 0);
    issue(1, 32);
    cp_wait1();
    __syncthreads();

    for (int i = 0; i < niter; i++) {
        const int s = i % NSTAGE;
        if (i + 2 < niter) issue((i + 2) % NSTAGE, (i + 2) * 32);
        else cp_commit();

        const unsigned sb = smem_u + (unsigned)s * HSTAGE_BYTES;

#pragma unroll
        for (int ks = 0; ks < 2; ks++) {
            const unsigned ko = (unsigned)(ks * 32);
            unsigned a[2][4];
            ldsm_x4(a[0][0], a[0][1], a[0][2], a[0][3], sb + aFr + ko);
            ldsm_x4(a[1][0], a[1][1], a[1][2], a[1][3], sb + aFr + 16 * HLD + ko);
            unsigned bf[4][4];
#pragma unroll
            for (int np = 0; np < 4; np++)
                ldsm_x4(bf[np][0], bf[np][1], bf[np][2], bf[np][3],
                        sb + bFr + (unsigned)(np * 16 * HLD) + ko);
#pragma unroll
            for (int nt = 0; nt < 8; nt++) {
                const unsigned b0 = bf[nt >> 1][(nt & 1) * 2];
                const unsigned b1 = bf[nt >> 1][(nt & 1) * 2 + 1];
                mma_f16(acc[0][nt], a[0][0], a[0][1], a[0][2], a[0][3], b0, b1);
                mma_f16(acc[1][nt], a[1][0], a[1][1], a[1][2], a[1][3], b0, b1);
            }
        }
        cp_wait1();
        __syncthreads();
    }

    // epilogue: c0/c1 at (row, 2t/2t+1); c2/c3 at row+8
#pragma unroll
    for (int mt = 0; mt < 2; mt++) {
#pragma unroll
        for (int nt = 0; nt < 8; nt++) {
            const int c = col0 + warp_n + nt * 8 + 2 * t;
            if (c < N) {
                const int r = row0 + warp_m + mt * 16 + g;
                *(float2*)&C[(size_t)r * N + c] =
                    make_float2(acc[mt][nt][0], acc[mt][nt][1]);
                *(float2*)&C[(size_t)(r + 8) * N + c] =
                    make_float2(acc[mt][nt][2], acc[mt][nt][3]);
            }
        }
    }
}

// ---------------------------------------------------------------------------
// Block reduction & elementwise kernels
// ---------------------------------------------------------------------------
__device__ __forceinline__ float block_reduce_sum_256(float v) {
    __shared__ float red[8];
    __shared__ float result;
    const int lane = threadIdx.x & 31;
    const int w = threadIdx.x >> 5;
#pragma unroll
    for (int o = 16; o > 0; o >>= 1)
        v += __shfl_xor_sync(0xffffffffu, v, o);
    if (lane == 0) red[w] = v;
    __syncthreads();
    if (threadIdx.x == 0) {
        float s = 0.f;
#pragma unroll
        for (int i = 0; i < 8; i++) s += red[i];
        result = s;
    }
    __syncthreads();
    return result;
}

// rmsnorm fp32 -> fp16 out (feeds GEMM3 A)
__global__ __launch_bounds__(256) void rmsnorm_h_kernel(
    const float* __restrict__ in, __half* __restrict__ out, int L)
{
    const size_t base = (size_t)blockIdx.x * L;
    float ss = 0.f;
    for (int i = threadIdx.x; i < L; i += 256) {
        float x = in[base + i];
        ss += x * x;
    }
    const float tot = block_reduce_sum_256(ss);
    const float r = rsqrtf(tot / (float)L + 1e-5f);
    for (int i = threadIdx.x; i < L; i += 256)
        out[base + i] = __float2half_rn(in[base + i] * r);
}

__global__ __launch_bounds__(256) void kvprep_kernel(
    const float* __restrict__ kvdr, const float* __restrict__ cosb,
    const float* __restrict__ sinb, __half* __restrict__ kvlat_h,
    float* __restrict__ krope)
{
    const int t = blockIdx.x;
    const int s = t & (SEQ - 1);
    const float* row = kvdr + (size_t)t * 576;

    float ss = 0.f;
    for (int i = threadIdx.x; i < 512; i += 256) {
        float x = row[i];
        ss += x * x;
    }
    const float tot = block_reduce_sum_256(ss);
    const float r = rsqrtf(tot / 512.f + 1e-5f);
    for (int i = threadIdx.x; i < 512; i += 256)
        kvlat_h[(size_t)t * 512 + i] = __float2half_rn(row[i] * r);

    if (threadIdx.x < 32) {
        const int i = threadIdx.x;
        const float x0 = row[512 + 2 * i];
        const float x1 = row[512 + 2 * i + 1];
        const float c  = cosb[s * 32 + i];
        const float sn = sinb[s * 32 + i];
        krope[(size_t)t * 64 + 2 * i]     = x0 * c - x1 * sn;
        krope[(size_t)t * 64 + 2 * i + 1] = x0 * sn + x1 * c;
    }
}

__global__ __launch_bounds__(256) void buildq_kernel(
    const float* __restrict__ qraw, const float* __restrict__ cosb,
    const float* __restrict__ sinb, float* __restrict__ gq)
{
    const int t = blockIdx.x;
    const int b = t >> 11;
    const int s = t & (SEQ - 1);
    const float* row = qraw + (size_t)t * 3072;

    for (int u = threadIdx.x; u < 512; u += 256) {
        const int h = u >> 5;
        const int p = u & 31;
        const float x0 = row[h * 192 + 128 + 2 * p];
        const float x1 = row[h * 192 + 128 + 2 * p + 1];
        const float c  = cosb[s * 32 + p];
        const float sn = sinb[s * 32 + p];
        const size_t o = ((size_t)(b * NH + h) * SEQ + s) * DQK;
        gq[o + 2 * p]     = x0 * c - x1 * sn;
        gq[o + 2 * p + 1] = x0 * sn + x1 * c;
    }
    for (int u = threadIdx.x; u < 2048; u += 256) {
        const int h = u >> 7;
        const int j = u & 127;
        const size_t o = ((size_t)(b * NH + h) * SEQ + s) * DQK;
        gq[o + 64 + j] = row[h * 192 + j];
    }
}

__global__ __launch_bounds__(256) void buildkv_kernel(
    const float* __restrict__ kv, const float* __restrict__ krope,
    float* __restrict__ gk, float* __restrict__ gv)
{
    const int t = blockIdx.x;
    const int b = t >> 11;
    const int s = t & (SEQ - 1);
    const float* kvrow = kv + (size_t)t * 4096;
    const float* krow = krope + (size_t)t * 64;

    for (int u = threadIdx.x; u < NH * DQK; u += 256) {
        const int h = u / DQK;
        const int d = u % DQK;
        const size_t o = ((size_t)(b * NH + h) * SEQ + s) * DQK;
        gk[o + d] = (d < 64) ? krow[d] : kvrow[h * 128 + (d - 64)];
    }
    for (int u = threadIdx.x; u < NH * DV; u += 256) {
        const int h = u >> 7;
        const int j = u & 127;
        const size_t o = ((size_t)(b * NH + h) * SEQ + s) * DV;
        gv[o + j] = kvrow[2048 + h * 128 + j];
    }
}

// ---------------------------------------------------------------------------
// Tensor-core flash attention (causal), tf32 mma (structure unchanged).
// Output: fp16 (feeds Wo GEMM A operand).
// ---------------------------------------------------------------------------
#define AQ_S 196
#define AV_S 136
#define AS_S 68
#define ATTN_SMEM_FLOATS (2 * 64 * AQ_S + 64 * AV_S + 64 * AS_S + 3 * 64)
#define ATTN_SMEM_BYTES (ATTN_SMEM_FLOATS * 4)

__global__ __launch_bounds__(256) void attn_tc_kernel(
    const float* __restrict__ gq, const float* __restrict__ gk,
    const float* __restrict__ gv, __half* __restrict__ gout)
{
    extern __shared__ float sm[];
    unsigned* Qs = (unsigned*)sm;
    unsigned* Ks = Qs + 64 * AQ_S;
    unsigned* Vs = Ks + 64 * AQ_S;
    float* Ss    = (float*)(Vs + 64 * AV_S);
    float* mrow  = Ss + 64 * AS_S;
    float* lrow  = mrow + 64;
    float* frow  = lrow + 64;

    const int tid  = threadIdx.x;
    const int lane = tid & 31;
    const int warp = tid >> 5;
    const int g = lane >> 2;
    const int t = lane & 3;
    const int warp_m  = (warp & 3) * 16;
    const int warp_nS = (warp >> 2) * 32;
    const int warp_nO = (warp >> 2) * 64;
    const int qt = blockIdx.x;
    const int bh = blockIdx.y;
    const int q0 = qt * 64;
    const float scale = 0.07216878364870323f;

    const size_t qk_base = (size_t)bh * SEQ * DQK;
    const size_t v_base  = (size_t)bh * SEQ * DV;

    for (int u = tid; u < 64 * 48; u += 256) {
        const int r = u / 48;
        const int c4 = (u % 48) * 4;
        const float4 v = *(const float4*)&gq[qk_base + (size_t)(q0 + r) * DQK + c4];
        Qs[r * AQ_S + c4 + 0] = tf32_rna(v.x);
        Qs[r * AQ_S + c4 + 1] = tf32_rna(v.y);
        Qs[r * AQ_S + c4 + 2] = tf32_rna(v.z);
        Qs[r * AQ_S + c4 + 3] = tf32_rna(v.w);
    }
    if (tid < 64) { mrow[tid] = -1e30f; lrow[tid] = 0.f; }

    float oacc[8][4];
#pragma unroll
    for (int nt = 0; nt < 8; nt++)
#pragma unroll
        for (int i = 0; i < 4; i++) oacc[nt][i] = 0.f;

    __syncthreads();

    for (int kt = 0; kt <= qt; kt++) {
        const int k0 = kt * 64;

        for (int u = tid; u < 64 * 48; u += 256) {
            const int r = u / 48;
            const int c4 = (u % 48) * 4;
            const float4 v = *(const float4*)&gk[qk_base + (size_t)(k0 + r) * DQK + c4];
            Ks[r * AQ_S + c4 + 0] = tf32_rna(v.x);
            Ks[r * AQ_S + c4 + 1] = tf32_rna(v.y);
            Ks[r * AQ_S + c4 + 2] = tf32_rna(v.z);
            Ks[r * AQ_S + c4 + 3] = tf32_rna(v.w);
        }
        for (int u = tid; u < 64 * 32; u += 256) {
            const int r = u >> 5;
            const int c4 = (u & 31) << 2;
            const float4 v = *(const float4*)&gv[v_base + (size_t)(k0 + r) * DV + c4];
            Vs[r * AV_S + c4 + 0] = tf32_rna(v.x);
            Vs[r * AV_S + c4 + 1] = tf32_rna(v.y);
            Vs[r * AV_S + c4 + 2] = tf32_rna(v.z);
            Vs[r * AV_S + c4 + 3] = tf32_rna(v.w);
        }
        __syncthreads();

        float sacc[4][4];
#pragma unroll
        for (int nt = 0; nt < 4; nt++)
#pragma unroll
            for (int i = 0; i < 4; i++) sacc[nt][i] = 0.f;

#pragma unroll
        for (int ks = 0; ks < 24; ks++) {
            const int kc = ks * 8;
            const unsigned a0 = Qs[(warp_m + g)     * AQ_S + kc + t];
            const unsigned a1 = Qs[(warp_m + g + 8) * AQ_S + kc + t];
            const unsigned a2 = Qs[(warp_m + g)     * AQ_S + kc + t + 4];
            const unsigned a3 = Qs[(warp_m + g + 8) * AQ_S + kc + t + 4];
#pragma unroll
            for (int nt = 0; nt < 4; nt++) {
                const int n = warp_nS + nt * 8 + g;
                const unsigned b0 = Ks[n * AQ_S + kc + t];
                const unsigned b1 = Ks[n * AQ_S + kc + t + 4];
                mma_tf32(sacc[nt], a0, a1, a2, a3, b0, b1);
            }
        }

        const bool diag = (kt == qt);
#pragma unroll
        for (int nt = 0; nt < 4; nt++) {
            const int col = warp_nS + nt * 8 + 2 * t;
            const int r0 = warp_m + g;
            const int r1 = r0 + 8;
            float s00 = sacc[nt][0] * scale, s01 = sacc[nt][1] * scale;
            float s10 = sacc[nt][2] * scale, s11 = sacc[nt][3] * scale;
            if (diag) {
                const int gi0 = q0 + r0, gi1 = q0 + r1;
                const int gj0 = k0 + col, gj1 = gj0 + 1;
                if (gj0 > gi0) s00 = -1e9f;
                if (gj1 > gi0) s01 = -1e9f;
                if (gj0 > gi1) s10 = -1e9f;
                if (gj1 > gi1) s11 = -1e9f;
            }
            *(float2*)&Ss[r0 * AS_S + col] = make_float2(s00, s01);
            *(float2*)&Ss[r1 * AS_S + col] = make_float2(s10, s11);
        }
        __syncthreads();

#pragma unroll
        for (int rr = 0; rr < 8; rr++) {
            const int i = warp * 8 + rr;
            const float x0 = Ss[i * AS_S + lane];
            const float x1 = Ss[i * AS_S + lane + 32];
            float mx = fmaxf(x0, x1);
#pragma unroll
            for (int o = 16; o > 0; o >>= 1)
                mx = fmaxf(mx, __shfl_xor_sync(0xffffffffu, mx, o));
            const float mold = mrow[i];
            const float mnew = fmaxf(mold, mx);
            const float p0 = __expf(x0 - mnew);
            const float p1 = __expf(x1 - mnew);
            float s = p0 + p1;
#pragma unroll
            for (int o = 16; o > 0; o >>= 1)
                s += __shfl_xor_sync(0xffffffffu, s, o);
            ((unsigned*)Ss)[i * AS_S + lane]      = tf32_rna(p0);
            ((unsigned*)Ss)[i * AS_S + lane + 32] = tf32_rna(p1);
            if (lane == 0) {
                const float f = __expf(mold - mnew);
                lrow[i] = lrow[i] * f + s;
                mrow[i] = mnew;
                frow[i] = f;
            }
        }
        __syncthreads();

        const float f0 = frow[warp_m + g];
        const float f1 = frow[warp_m + g + 8];
#pragma unroll
        for (int nt = 0; nt < 8; nt++) {
            oacc[nt][0] *= f0; oacc[nt][1] *= f0;
            oacc[nt][2] *= f1; oacc[nt][3] *= f1;
        }
        const unsigned* Psu = (const unsigned*)Ss;
#pragma unroll
        for (int ks = 0; ks < 8; ks++) {
            const int kc = ks * 8;
            const unsigned a0 = Psu[(warp_m + g)     * AS_S + kc + t];
            const unsigned a1 = Psu[(warp_m + g + 8) * AS_S + kc + t];
            const unsigned a2 = Psu[(warp_m + g)     * AS_S + kc + t + 4];
            const unsigned a3 = Psu[(warp_m + g + 8) * AS_S + kc + t + 4];
#pragma unroll
            for (int nt = 0; nt < 8; nt++) {
                const int col = warp_nO + nt * 8 + g;
                const unsigned b0 = Vs[(kc + t)     * AV_S + col];
                const unsigned b1 = Vs[(kc + t + 4) * AV_S + col];
                mma_tf32(oacc[nt], a0, a1, a2, a3, b0, b1);
            }
        }
        __syncthreads();
    }

    // epilogue: normalize, write fp16 (feeds Wo GEMM)
    const int b = bh >> 4;
    const int h = bh & 15;
    const float inv0 = 1.0f / lrow[warp_m + g];
    const float inv1 = 1.0f / lrow[warp_m + g + 8];
    const size_t row0 = (size_t)(b * SEQ + q0 + warp_m + g) * 2048 + h * DV;
    const size_t row1 = row0 + 8 * 2048;
#pragma unroll
    for (int nt = 0; nt < 8; nt++) {
        const int col = warp_nO + nt * 8 + 2 * t;
        *(__half2*)&gout[row0 + col] =
            __floats2half2_rn(oacc[nt][0] * inv0, oacc[nt][1] * inv0);
        *(__half2*)&gout[row1 + col] =
            __floats2half2_rn(oacc[nt][2] * inv1, oacc[nt][3] * inv1);
    }
}

// ---------------------------------------------------------------------------
// launch
// ---------------------------------------------------------------------------
extern "C" void kernel_launch(void* const* d_in, const int* in_sizes, int n_in,
                              void* d_out, int out_size)
{
    const float* hidden   = (const float*)d_in[0];
    const float* cosb     = (const float*)d_in[2];
    const float* sinb     = (const float*)d_in[3];
    const float* Wq_down  = (const float*)d_in[4];
    const float* Wkv_down = (const float*)d_in[5];
    const float* Wq_up    = (const float*)d_in[6];
    const float* Wkv_up   = (const float*)d_in[7];
    const float* Wo       = (const float*)d_in[8];
    float* out = (float*)d_out;

    float *qlat, *kvdr, *krope, *qraw, *kv, *q, *k, *v;
    __half *hidh, *qlath, *kvlath, *attnh, *w1h, *w2h, *w3h, *w4h, *w5h;
    cudaGetSymbolAddress((void**)&qlat,   g_qlat);
    cudaGetSymbolAddress((void**)&kvdr,   g_kvdr);
    cudaGetSymbolAddress((void**)&krope,  g_krope);
    cudaGetSymbolAddress((void**)&qraw,   g_qraw);
    cudaGetSymbolAddress((void**)&kv,     g_kv);
    cudaGetSymbolAddress((void**)&q,      g_q);
    cudaGetSymbolAddress((void**)&k,      g_k);
    cudaGetSymbolAddress((void**)&v,      g_v);
    cudaGetSymbolAddress((void**)&hidh,   g_hid_h);
    cudaGetSymbolAddress((void**)&qlath,  g_qlat_h);
    cudaGetSymbolAddress((void**)&kvlath, g_kvlat_h);
    cudaGetSymbolAddress((void**)&attnh,  g_attn_h);
    cudaGetSymbolAddress((void**)&w1h,    g_w1h);
    cudaGetSymbolAddress((void**)&w2h,    g_w2h);
    cudaGetSymbolAddress((void**)&w3h,    g_w3h);
    cudaGetSymbolAddress((void**)&w4h,    g_w4h);
    cudaGetSymbolAddress((void**)&w5h,    g_w5h);

    cudaFuncSetAttribute(attn_tc_kernel,
                         cudaFuncAttributeMaxDynamicSharedMemorySize,
                         ATTN_SMEM_BYTES);
    cudaFuncSetAttribute(gemm_f16_pipe,
                         cudaFuncAttributeMaxDynamicSharedMemorySize,
                         GEMM_SMEM_BYTES);

    // 0a. hidden -> fp16
    cvt_f16_kernel<<<(4096 * 2048 / 4 + 255) / 256, 256>>>(hidden, hidh, 4096 * 2048 / 4);
    // 0b. weights: transpose + fp16, W[K][N] -> Wt[N][K]
    wtrans_h_kernel<<<dim3(1536 / 32, 2048 / 32), 256>>>(Wq_down,  w1h, 2048, 1536);
    wtrans_h_kernel<<<dim3(576  / 32, 2048 / 32), 256>>>(Wkv_down, w2h, 2048, 576);
    wtrans_h_kernel<<<dim3(3072 / 32, 1536 / 32), 256>>>(Wq_up,    w3h, 1536, 3072);
    wtrans_h_kernel<<<dim3(4096 / 32, 512  / 32), 256>>>(Wkv_up,   w4h, 512,  4096);
    wtrans_h_kernel<<<dim3(2048 / 32, 2048 / 32), 256>>>(Wo,       w5h, 2048, 2048);

    // 1. q latent = hidden @ Wq_down
    gemm_f16_pipe<<<dim3(12, 32), 256, GEMM_SMEM_BYTES>>>(hidh, w1h, qlat, TOK, 1536, 2048);
    // 2. kvdr = hidden @ Wkv_down
    gemm_f16_pipe<<<dim3(5, 32), 256, GEMM_SMEM_BYTES>>>(hidh, w2h, kvdr, TOK, 576, 2048);
    // 3. rmsnorm q latent -> fp16
    rmsnorm_h_kernel<<<TOK, 256>>>(qlat, qlath, 1536);
    // 4. kv latent rmsnorm (-> fp16) + k_rope rope
    kvprep_kernel<<<TOK, 256>>>(kvdr, cosb, sinb, kvlath, krope);
    // 5. q raw = qlat @ Wq_up
    gemm_f16_pipe<<<dim3(24, 32), 256, GEMM_SMEM_BYTES>>>(qlath, w3h, qraw, TOK, 3072, 1536);
    // 6. kv = kvlat @ Wkv_up
    gemm_f16_pipe<<<dim3(32, 32), 256, GEMM_SMEM_BYTES>>>(kvlath, w4h, kv, TOK, 4096, 512);
    // 7. build q
    buildq_kernel<<<TOK, 256>>>(qraw, cosb, sinb, q);
    // 8. build k, v
    buildkv_kernel<<<TOK, 256>>>(kv, krope, k, v);
    // 9. tensor-core flash attention (-> fp16 out)
    attn_tc_kernel<<<dim3(SEQ / 64, 2 * NH), 256, ATTN_SMEM_BYTES>>>(q, k, v, attnh);
    // 10. out = attn @ Wo
    gemm_f16_pipe<<<dim3(16, 32), 256, GEMM_SMEM_BYTES>>>(attnh, w5h, out, TOK, 2048, 2048);
}

// round 17
// speedup vs baseline: 1.7408x; 1.4076x over previous
#include <cuda_runtime.h>
#include <cuda_fp16.h>
#include <math.h>
#include <stdint.h>

// ---------------------------------------------------------------------------
// Problem constants: B=2, S=2048, D=2048, H=16, NOPE=128, ROPE=64, DV=128,
// DQK=192, QLR=1536, KVLR=512, tokens = 4096
// ---------------------------------------------------------------------------
#define TOK 4096
#define SEQ 2048
#define NH 16
#define DQK 192
#define DV 128

// ---------------------------------------------------------------------------
// Device scratch (static, allocation-free)
// ---------------------------------------------------------------------------
__device__ float  g_qlat [4096 * 1536];
__device__ float  g_kvdr [4096 * 576];
__device__ float  g_krope[4096 * 64];
__device__ float  g_qraw [4096L * 3072];
__device__ float  g_kv   [4096L * 4096];
__device__ float  g_q    [32L * 2048 * 192];
__device__ float  g_k    [32L * 2048 * 192];
__device__ float  g_v    [32L * 2048 * 128];
// fp16 GEMM operands
__device__ __half g_hid_h [4096L * 2048];
__device__ __half g_qlat_h[4096L * 1536];
__device__ __half g_kvlat_h[4096L * 512];
__device__ __half g_attn_h[4096L * 2048];
__device__ __half g_w1h [1536L * 2048];
__device__ __half g_w2h [576L  * 2048];
__device__ __half g_w3h [3072L * 1536];
__device__ __half g_w4h [4096L * 512];
__device__ __half g_w5h [2048L * 2048];

// ---------------------------------------------------------------------------
// helpers
// ---------------------------------------------------------------------------
__device__ __forceinline__ void mma_f16(
    float* c, unsigned a0, unsigned a1, unsigned a2, unsigned a3,
    unsigned b0, unsigned b1)
{
    asm volatile(
        "mma.sync.aligned.m16n8k16.row.col.f32.f16.f16.f32 "
        "{%0,%1,%2,%3}, {%4,%5,%6,%7}, {%8,%9}, {%0,%1,%2,%3};\n"
        : "+f"(c[0]), "+f"(c[1]), "+f"(c[2]), "+f"(c[3])
        : "r"(a0), "r"(a1), "r"(a2), "r"(a3), "r"(b0), "r"(b1));
}

__device__ __forceinline__ unsigned smem_u32(const void* p) {
    unsigned a;
    asm("{ .reg .u64 t; cvta.to.shared.u64 t, %1; cvt.u32.u64 %0, t; }"
        : "=r"(a) : "l"(p));
    return a;
}
__device__ __forceinline__ void cp_async16(unsigned dst, const void* src) {
    asm volatile("cp.async.ca.shared.global [%0], [%1], 16;\n" :: "r"(dst), "l"(src));
}
__device__ __forceinline__ void cp_async16z(unsigned dst, const void* src, int srcsz) {
    asm volatile("cp.async.ca.shared.global [%0], [%1], 16, %2;\n"
                 :: "r"(dst), "l"(src), "r"(srcsz));
}
__device__ __forceinline__ void cp_commit() {
    asm volatile("cp.async.commit_group;\n");
}
__device__ __forceinline__ void cp_wait1() {
    asm volatile("cp.async.wait_group 1;\n");
}
__device__ __forceinline__ void ldsm_x4(
    unsigned& r0, unsigned& r1, unsigned& r2, unsigned& r3, unsigned addr)
{
    asm volatile("ldmatrix.sync.aligned.m8n8.x4.shared.b16 {%0,%1,%2,%3}, [%4];"
                 : "=r"(r0), "=r"(r1), "=r"(r2), "=r"(r3) : "r"(addr));
}
__device__ __forceinline__ void ldsm_x4_t(
    unsigned& r0, unsigned& r1, unsigned& r2, unsigned& r3, unsigned addr)
{
    asm volatile("ldmatrix.sync.aligned.m8n8.x4.trans.shared.b16 {%0,%1,%2,%3}, [%4];"
                 : "=r"(r0), "=r"(r1), "=r"(r2), "=r"(r3) : "r"(addr));
}

// ---------------------------------------------------------------------------
// fp32 -> fp16 convert (n4 = element count / 4)
// ---------------------------------------------------------------------------
__global__ __launch_bounds__(256) void cvt_f16_kernel(
    const float* __restrict__ in, __half* __restrict__ out, int n4)
{
    const int i = blockIdx.x * 256 + threadIdx.x;
    if (i < n4) {
        const float4 v = ((const float4*)in)[i];
        __half2* o = (__half2*)(out + (size_t)i * 4);
        o[0] = __floats2half2_rn(v.x, v.y);
        o[1] = __floats2half2_rn(v.z, v.w);
    }
}

// ---------------------------------------------------------------------------
// Weight transpose + fp16: in[K][N] fp32 -> out[N][K] half. K,N % 32 == 0.
// ---------------------------------------------------------------------------
__global__ __launch_bounds__(256) void wtrans_h_kernel(
    const float* __restrict__ in, __half* __restrict__ out, int K, int N)
{
    __shared__ float ts[32][33];
    const int n0 = blockIdx.x * 32;
    const int k0 = blockIdx.y * 32;
    const int tx = threadIdx.x & 31;
    const int ty = threadIdx.x >> 5;
#pragma unroll
    for (int p = 0; p < 4; p++)
        ts[ty + p * 8][tx] = in[(size_t)(k0 + ty + p * 8) * N + n0 + tx];
    __syncthreads();
#pragma unroll
    for (int p = 0; p < 4; p++)
        out[(size_t)(n0 + ty + p * 8) * K + k0 + tx] =
            __float2half_rn(ts[tx][ty + p * 8]);
}

// ---------------------------------------------------------------------------
// fp16 tensor-core GEMM (as R16 WIN) + 2 CTAs/SM.
// ---------------------------------------------------------------------------
#define HLD 80
#define HSTAGE_BYTES (2 * 128 * HLD)
#define NSTAGE 3
#define GEMM_SMEM_BYTES (NSTAGE * HSTAGE_BYTES)

__global__ __launch_bounds__(256, 2) void gemm_f16_pipe(
    const __half* __restrict__ A, const __half* __restrict__ Bt,
    float* __restrict__ C, int M, int N, int K)
{
    extern __shared__ char smc[];
    const unsigned smem_u = smem_u32(smc);

    const int tid  = threadIdx.x;
    const int lane = tid & 31;
    const int warp = tid >> 5;
    const int g = lane >> 2;
    const int t = lane & 3;
    const int warp_m = (warp & 3) * 32;
    const int warp_n = (warp >> 2) * 64;
    const int row0 = blockIdx.y * 128;
    const int col0 = blockIdx.x * 128;

    const int lrow  = tid >> 1;
    const int lhalf = tid & 1;
    const __half* aSrc = A  + (size_t)(row0 + lrow) * K + lhalf * 16;
    const __half* bSrc = Bt + (size_t)(col0 + lrow) * K + lhalf * 16;
    const int bok = (col0 + lrow < N) ? 16 : 0;
    const unsigned aDst = (unsigned)(lrow * HLD + lhalf * 32);
    const unsigned bDst = (unsigned)(128 * HLD + lrow * HLD + lhalf * 32);

    auto issue = [&](int s, int k0) {
        const unsigned sb = smem_u + (unsigned)s * HSTAGE_BYTES;
        cp_async16(sb + aDst,      aSrc + k0);
        cp_async16(sb + aDst + 16, aSrc + k0 + 8);
        cp_async16z(sb + bDst,      bSrc + k0,     bok);
        cp_async16z(sb + bDst + 16, bSrc + k0 + 8, bok);
        cp_commit();
    };

    const unsigned aFr = (unsigned)((warp_m + (lane & 15)) * HLD + ((lane >> 4) << 4));
    const unsigned bFr = (unsigned)(128 * HLD +
        (warp_n + (lane & 7) + ((lane & 16) >> 1)) * HLD + ((lane & 8) << 1));

    float acc[2][8][4];
#pragma unroll
    for (int mt = 0; mt < 2; mt++)
#pragma unroll
        for (int nt = 0; nt < 8; nt++)
#pragma unroll
            for (int i = 0; i < 4; i++) acc[mt][nt][i] = 0.f;

    const int niter = K >> 5;

    issue(0, 0);
    issue(1, 32);
    cp_wait1();
    __syncthreads();

    for (int i = 0; i < niter; i++) {
        const int s = i % NSTAGE;
        if (i + 2 < niter) issue((i + 2) % NSTAGE, (i + 2) * 32);
        else cp_commit();

        const unsigned sb = smem_u + (unsigned)s * HSTAGE_BYTES;

#pragma unroll
        for (int ks = 0; ks < 2; ks++) {
            const unsigned ko = (unsigned)(ks * 32);
            unsigned a[2][4];
            ldsm_x4(a[0][0], a[0][1], a[0][2], a[0][3], sb + aFr + ko);
            ldsm_x4(a[1][0], a[1][1], a[1][2], a[1][3], sb + aFr + 16 * HLD + ko);
            unsigned bf[4][4];
#pragma unroll
            for (int np = 0; np < 4; np++)
                ldsm_x4(bf[np][0], bf[np][1], bf[np][2], bf[np][3],
                        sb + bFr + (unsigned)(np * 16 * HLD) + ko);
#pragma unroll
            for (int nt = 0; nt < 8; nt++) {
                const unsigned b0 = bf[nt >> 1][(nt & 1) * 2];
                const unsigned b1 = bf[nt >> 1][(nt & 1) * 2 + 1];
                mma_f16(acc[0][nt], a[0][0], a[0][1], a[0][2], a[0][3], b0, b1);
                mma_f16(acc[1][nt], a[1][0], a[1][1], a[1][2], a[1][3], b0, b1);
            }
        }
        cp_wait1();
        __syncthreads();
    }

#pragma unroll
    for (int mt = 0; mt < 2; mt++) {
#pragma unroll
        for (int nt = 0; nt < 8; nt++) {
            const int c = col0 + warp_n + nt * 8 + 2 * t;
            if (c < N) {
                const int r = row0 + warp_m + mt * 16 + g;
                *(float2*)&C[(size_t)r * N + c] =
                    make_float2(acc[mt][nt][0], acc[mt][nt][1]);
                *(float2*)&C[(size_t)(r + 8) * N + c] =
                    make_float2(acc[mt][nt][2], acc[mt][nt][3]);
            }
        }
    }
}

// ---------------------------------------------------------------------------
// Block reduction & elementwise kernels
// ---------------------------------------------------------------------------
__device__ __forceinline__ float block_reduce_sum_256(float v) {
    __shared__ float red[8];
    __shared__ float result;
    const int lane = threadIdx.x & 31;
    const int w = threadIdx.x >> 5;
#pragma unroll
    for (int o = 16; o > 0; o >>= 1)
        v += __shfl_xor_sync(0xffffffffu, v, o);
    if (lane == 0) red[w] = v;
    __syncthreads();
    if (threadIdx.x == 0) {
        float s = 0.f;
#pragma unroll
        for (int i = 0; i < 8; i++) s += red[i];
        result = s;
    }
    __syncthreads();
    return result;
}

__global__ __launch_bounds__(256) void rmsnorm_h_kernel(
    const float* __restrict__ in, __half* __restrict__ out, int L)
{
    const size_t base = (size_t)blockIdx.x * L;
    float ss = 0.f;
    for (int i = threadIdx.x; i < L; i += 256) {
        float x = in[base + i];
        ss += x * x;
    }
    const float tot = block_reduce_sum_256(ss);
    const float r = rsqrtf(tot / (float)L + 1e-5f);
    for (int i = threadIdx.x; i < L; i += 256)
        out[base + i] = __float2half_rn(in[base + i] * r);
}

__global__ __launch_bounds__(256) void kvprep_kernel(
    const float* __restrict__ kvdr, const float* __restrict__ cosb,
    const float* __restrict__ sinb, __half* __restrict__ kvlat_h,
    float* __restrict__ krope)
{
    const int t = blockIdx.x;
    const int s = t & (SEQ - 1);
    const float* row = kvdr + (size_t)t * 576;

    float ss = 0.f;
    for (int i = threadIdx.x; i < 512; i += 256) {
        float x = row[i];
        ss += x * x;
    }
    const float tot = block_reduce_sum_256(ss);
    const float r = rsqrtf(tot / 512.f + 1e-5f);
    for (int i = threadIdx.x; i < 512; i += 256)
        kvlat_h[(size_t)t * 512 + i] = __float2half_rn(row[i] * r);

    if (threadIdx.x < 32) {
        const int i = threadIdx.x;
        const float x0 = row[512 + 2 * i];
        const float x1 = row[512 + 2 * i + 1];
        const float c  = cosb[s * 32 + i];
        const float sn = sinb[s * 32 + i];
        krope[(size_t)t * 64 + 2 * i]     = x0 * c - x1 * sn;
        krope[(size_t)t * 64 + 2 * i + 1] = x0 * sn + x1 * c;
    }
}

__global__ __launch_bounds__(256) void buildq_kernel(
    const float* __restrict__ qraw, const float* __restrict__ cosb,
    const float* __restrict__ sinb, float* __restrict__ gq)
{
    const int t = blockIdx.x;
    const int b = t >> 11;
    const int s = t & (SEQ - 1);
    const float* row = qraw + (size_t)t * 3072;

    for (int u = threadIdx.x; u < 512; u += 256) {
        const int h = u >> 5;
        const int p = u & 31;
        const float x0 = row[h * 192 + 128 + 2 * p];
        const float x1 = row[h * 192 + 128 + 2 * p + 1];
        const float c  = cosb[s * 32 + p];
        const float sn = sinb[s * 32 + p];
        const size_t o = ((size_t)(b * NH + h) * SEQ + s) * DQK;
        gq[o + 2 * p]     = x0 * c - x1 * sn;
        gq[o + 2 * p + 1] = x0 * sn + x1 * c;
    }
    for (int u = threadIdx.x; u < 2048; u += 256) {
        const int h = u >> 7;
        const int j = u & 127;
        const size_t o = ((size_t)(b * NH + h) * SEQ + s) * DQK;
        gq[o + 64 + j] = row[h * 192 + j];
    }
}

__global__ __launch_bounds__(256) void buildkv_kernel(
    const float* __restrict__ kv, const float* __restrict__ krope,
    float* __restrict__ gk, float* __restrict__ gv)
{
    const int t = blockIdx.x;
    const int b = t >> 11;
    const int s = t & (SEQ - 1);
    const float* kvrow = kv + (size_t)t * 4096;
    const float* krow = krope + (size_t)t * 64;

    for (int u = threadIdx.x; u < NH * DQK; u += 256) {
        const int h = u / DQK;
        const int d = u % DQK;
        const size_t o = ((size_t)(b * NH + h) * SEQ + s) * DQK;
        gk[o + d] = (d < 64) ? krow[d] : kvrow[h * 128 + (d - 64)];
    }
    for (int u = threadIdx.x; u < NH * DV; u += 256) {
        const int h = u >> 7;
        const int j = u & 127;
        const size_t o = ((size_t)(b * NH + h) * SEQ + s) * DV;
        gv[o + j] = kvrow[2048 + h * 128 + j];
    }
}

// ---------------------------------------------------------------------------
// fp16 tensor-core flash attention (causal). BQ=BK=64, 256 threads
// (8 warps, 4x2: warp = 16 q-rows x {32 score cols | 64 out cols}).
// fp32 online softmax; fp16 m16n8k16 MMA for QK^T (plain ldmatrix on Q,K)
// and P@V (plain ldmatrix on P, trans ldmatrix on row-major V).
// Smem strides (halves): Q/K 200 (400B row), V 136 (272B), P 72 (144B) —
// all == 4 banks mod 32 per row => conflict-free ldmatrix phases.
// ---------------------------------------------------------------------------
#define AQH 200
#define AVH 136
#define APH 72
#define AS_S 68
#define ATTN_SMEM_BYTES (2 * 64 * AQH * 2 + 64 * AVH * 2 + 64 * AS_S * 4 + \
                         64 * APH * 2 + 3 * 64 * 4)

__global__ __launch_bounds__(256) void attn_h_kernel(
    const float* __restrict__ gq, const float* __restrict__ gk,
    const float* __restrict__ gv, __half* __restrict__ gout)
{
    extern __shared__ char smc[];
    __half* Qh = (__half*)smc;                    // 64 x AQH
    __half* Kh = Qh + 64 * AQH;                   // 64 x AQH
    __half* Vh = Kh + 64 * AQH;                   // 64 x AVH
    float*  Ss = (float*)(Vh + 64 * AVH);         // 64 x AS_S
    __half* Ph = (__half*)(Ss + 64 * AS_S);       // 64 x APH
    float*  mrow = (float*)(Ph + 64 * APH);
    float*  lrow = mrow + 64;
    float*  frow = lrow + 64;

    const unsigned sb = smem_u32(smc);
    const unsigned Qb = sb;
    const unsigned Kb = sb + 64 * AQH * 2;
    const unsigned Vb = Kb + 64 * AQH * 2;
    const unsigned Pb = (unsigned)(sb + ((char*)Ph - smc));

    const int tid  = threadIdx.x;
    const int lane = tid & 31;
    const int warp = tid >> 5;
    const int g = lane >> 2;
    const int t = lane & 3;
    const int warp_m  = (warp & 3) * 16;
    const int warp_nS = (warp >> 2) * 32;
    const int warp_nO = (warp >> 2) * 64;
    const int qt = blockIdx.x;
    const int bh = blockIdx.y;
    const int q0 = qt * 64;
    const float scale = 0.07216878364870323f;

    const size_t qk_base = (size_t)bh * SEQ * DQK;
    const size_t v_base  = (size_t)bh * SEQ * DV;

    // fragment base addresses
    const unsigned aQfr = Qb + (unsigned)((warp_m + (lane & 15)) * AQH * 2 + ((lane >> 4) << 4));
    const unsigned bKfr = Kb + (unsigned)((warp_nS + (lane & 7) + ((lane & 16) >> 1)) * AQH * 2 + ((lane & 8) << 1));
    const unsigned aPfr = Pb + (unsigned)((warp_m + (lane & 15)) * APH * 2 + ((lane >> 4) << 4));
    const unsigned bVfr = Vb + (unsigned)((lane & 15) * AVH * 2 + (warp_nO + ((lane >> 4) << 3)) * 2);

    // load Q tile -> half smem
    for (int u = tid; u < 64 * 48; u += 256) {
        const int r = u / 48;
        const int c4 = (u % 48) * 4;
        const float4 v = *(const float4*)&gq[qk_base + (size_t)(q0 + r) * DQK + c4];
        __half2* dst = (__half2*)&Qh[r * AQH + c4];
        dst[0] = __floats2half2_rn(v.x, v.y);
        dst[1] = __floats2half2_rn(v.z, v.w);
    }
    if (tid < 64) { mrow[tid] = -1e30f; lrow[tid] = 0.f; }

    float oacc[8][4];
#pragma unroll
    for (int nt = 0; nt < 8; nt++)
#pragma unroll
        for (int i = 0; i < 4; i++) oacc[nt][i] = 0.f;

    __syncthreads();

    for (int kt = 0; kt <= qt; kt++) {
        const int k0 = kt * 64;

        // load K, V tiles -> half smem
        for (int u = tid; u < 64 * 48; u += 256) {
            const int r = u / 48;
            const int c4 = (u % 48) * 4;
            const float4 v = *(const float4*)&gk[qk_base + (size_t)(k0 + r) * DQK + c4];
            __half2* dst = (__half2*)&Kh[r * AQH + c4];
            dst[0] = __floats2half2_rn(v.x, v.y);
            dst[1] = __floats2half2_rn(v.z, v.w);
        }
        for (int u = tid; u < 64 * 32; u += 256) {
            const int r = u >> 5;
            const int c4 = (u & 31) << 2;
            const float4 v = *(const float4*)&gv[v_base + (size_t)(k0 + r) * DV + c4];
            __half2* dst = (__half2*)&Vh[r * AVH + c4];
            dst[0] = __floats2half2_rn(v.x, v.y);
            dst[1] = __floats2half2_rn(v.z, v.w);
        }
        __syncthreads();

        // --- S = Q @ K^T : 12 k16-steps, warp tile 16x32 ---
        float sacc[4][4];
#pragma unroll
        for (int nt = 0; nt < 4; nt++)
#pragma unroll
            for (int i = 0; i < 4; i++) sacc[nt][i] = 0.f;

#pragma unroll
        for (int ks = 0; ks < 12; ks++) {
            const unsigned ko = (unsigned)(ks * 32);   // 16 halves
            unsigned a0, a1, a2, a3;
            ldsm_x4(a0, a1, a2, a3, aQfr + ko);
            unsigned bf[2][4];
#pragma unroll
            for (int np = 0; np < 2; np++)
                ldsm_x4(bf[np][0], bf[np][1], bf[np][2], bf[np][3],
                        bKfr + (unsigned)(np * 16 * AQH * 2) + ko);
#pragma unroll
            for (int nt = 0; nt < 4; nt++)
                mma_f16(sacc[nt], a0, a1, a2, a3,
                        bf[nt >> 1][(nt & 1) * 2], bf[nt >> 1][(nt & 1) * 2 + 1]);
        }

        // scale + causal mask + write scores (fp32) to smem
        const bool diag = (kt == qt);
#pragma unroll
        for (int nt = 0; nt < 4; nt++) {
            const int col = warp_nS + nt * 8 + 2 * t;
            const int r0 = warp_m + g;
            const int r1 = r0 + 8;
            float s00 = sacc[nt][0] * scale, s01 = sacc[nt][1] * scale;
            float s10 = sacc[nt][2] * scale, s11 = sacc[nt][3] * scale;
            if (diag) {
                const int gi0 = q0 + r0, gi1 = q0 + r1;
                const int gj0 = k0 + col, gj1 = gj0 + 1;
                if (gj0 > gi0) s00 = -1e9f;
                if (gj1 > gi0) s01 = -1e9f;
                if (gj0 > gi1) s10 = -1e9f;
                if (gj1 > gi1) s11 = -1e9f;
            }
            *(float2*)&Ss[r0 * AS_S + col] = make_float2(s00, s01);
            *(float2*)&Ss[r1 * AS_S + col] = make_float2(s10, s11);
        }
        __syncthreads();

        // --- online softmax: warp w owns rows w*8..w*8+7; P -> half smem ---
#pragma unroll
        for (int rr = 0; rr < 8; rr++) {
            const int i = warp * 8 + rr;
            const float x0 = Ss[i * AS_S + lane];
            const float x1 = Ss[i * AS_S + lane + 32];
            float mx = fmaxf(x0, x1);
#pragma unroll
            for (int o = 16; o > 0; o >>= 1)
                mx = fmaxf(mx, __shfl_xor_sync(0xffffffffu, mx, o));
            const float mold = mrow[i];
            const float mnew = fmaxf(mold, mx);
            const float p0 = __expf(x0 - mnew);
            const float p1 = __expf(x1 - mnew);
            float s = p0 + p1;
#pragma unroll
            for (int o = 16; o > 0; o >>= 1)
                s += __shfl_xor_sync(0xffffffffu, s, o);
            Ph[i * APH + lane]      = __float2half_rn(p0);
            Ph[i * APH + lane + 32] = __float2half_rn(p1);
            if (lane == 0) {
                const float f = __expf(mold - mnew);
                lrow[i] = lrow[i] * f + s;
                mrow[i] = mnew;
                frow[i] = f;
            }
        }
        __syncthreads();

        // --- O = O * f + P @ V : 4 k16-steps, warp tile 16x64 ---
        const float f0 = frow[warp_m + g];
        const float f1 = frow[warp_m + g + 8];
#pragma unroll
        for (int nt = 0; nt < 8; nt++) {
            oacc[nt][0] *= f0; oacc[nt][1] *= f0;
            oacc[nt][2] *= f1; oacc[nt][3] *= f1;
        }
#pragma unroll
        for (int ks = 0; ks < 4; ks++) {
            unsigned a0, a1, a2, a3;
            ldsm_x4(a0, a1, a2, a3, aPfr + (unsigned)(ks * 32));
            unsigned vf[4][4];
#pragma unroll
            for (int np = 0; np < 4; np++)
                ldsm_x4_t(vf[np][0], vf[np][1], vf[np][2], vf[np][3],
                          bVfr + (unsigned)(ks * 16 * AVH * 2) + (unsigned)(np * 32));
#pragma unroll
            for (int nt = 0; nt < 8; nt++)
                mma_f16(oacc[nt], a0, a1, a2, a3,
                        vf[nt >> 1][(nt & 1) * 2], vf[nt >> 1][(nt & 1) * 2 + 1]);
        }
        __syncthreads();
    }

    // epilogue: normalize, write fp16 (feeds Wo GEMM)
    const int b = bh >> 4;
    const int h = bh & 15;
    const float inv0 = 1.0f / lrow[warp_m + g];
    const float inv1 = 1.0f / lrow[warp_m + g + 8];
    const size_t row0 = (size_t)(b * SEQ + q0 + warp_m + g) * 2048 + h * DV;
    const size_t row1 = row0 + 8 * 2048;
#pragma unroll
    for (int nt = 0; nt < 8; nt++) {
        const int col = warp_nO + nt * 8 + 2 * t;
        *(__half2*)&gout[row0 + col] =
            __floats2half2_rn(oacc[nt][0] * inv0, oacc[nt][1] * inv0);
        *(__half2*)&gout[row1 + col] =
            __floats2half2_rn(oacc[nt][2] * inv1, oacc[nt][3] * inv1);
    }
}

// ---------------------------------------------------------------------------
// launch
// ---------------------------------------------------------------------------
extern "C" void kernel_launch(void* const* d_in, const int* in_sizes, int n_in,
                              void* d_out, int out_size)
{
    const float* hidden   = (const float*)d_in[0];
    const float* cosb     = (const float*)d_in[2];
    const float* sinb     = (const float*)d_in[3];
    const float* Wq_down  = (const float*)d_in[4];
    const float* Wkv_down = (const float*)d_in[5];
    const float* Wq_up    = (const float*)d_in[6];
    const float* Wkv_up   = (const float*)d_in[7];
    const float* Wo       = (const float*)d_in[8];
    float* out = (float*)d_out;

    float *qlat, *kvdr, *krope, *qraw, *kv, *q, *k, *v;
    __half *hidh, *qlath, *kvlath, *attnh, *w1h, *w2h, *w3h, *w4h, *w5h;
    cudaGetSymbolAddress((void**)&qlat,   g_qlat);
    cudaGetSymbolAddress((void**)&kvdr,   g_kvdr);
    cudaGetSymbolAddress((void**)&krope,  g_krope);
    cudaGetSymbolAddress((void**)&qraw,   g_qraw);
    cudaGetSymbolAddress((void**)&kv,     g_kv);
    cudaGetSymbolAddress((void**)&q,      g_q);
    cudaGetSymbolAddress((void**)&k,      g_k);
    cudaGetSymbolAddress((void**)&v,      g_v);
    cudaGetSymbolAddress((void**)&hidh,   g_hid_h);
    cudaGetSymbolAddress((void**)&qlath,  g_qlat_h);
    cudaGetSymbolAddress((void**)&kvlath, g_kvlat_h);
    cudaGetSymbolAddress((void**)&attnh,  g_attn_h);
    cudaGetSymbolAddress((void**)&w1h,    g_w1h);
    cudaGetSymbolAddress((void**)&w2h,    g_w2h);
    cudaGetSymbolAddress((void**)&w3h,    g_w3h);
    cudaGetSymbolAddress((void**)&w4h,    g_w4h);
    cudaGetSymbolAddress((void**)&w5h,    g_w5h);

    cudaFuncSetAttribute(attn_h_kernel,
                         cudaFuncAttributeMaxDynamicSharedMemorySize,
                         ATTN_SMEM_BYTES);
    cudaFuncSetAttribute(gemm_f16_pipe,
                         cudaFuncAttributeMaxDynamicSharedMemorySize,
                         GEMM_SMEM_BYTES);

    // 0a. hidden -> fp16
    cvt_f16_kernel<<<(4096 * 2048 / 4 + 255) / 256, 256>>>(hidden, hidh, 4096 * 2048 / 4);
    // 0b. weights: transpose + fp16
    wtrans_h_kernel<<<dim3(1536 / 32, 2048 / 32), 256>>>(Wq_down,  w1h, 2048, 1536);
    wtrans_h_kernel<<<dim3(576  / 32, 2048 / 32), 256>>>(Wkv_down, w2h, 2048, 576);
    wtrans_h_kernel<<<dim3(3072 / 32, 1536 / 32), 256>>>(Wq_up,    w3h, 1536, 3072);
    wtrans_h_kernel<<<dim3(4096 / 32, 512  / 32), 256>>>(Wkv_up,   w4h, 512,  4096);
    wtrans_h_kernel<<<dim3(2048 / 32, 2048 / 32), 256>>>(Wo,       w5h, 2048, 2048);

    // 1. q latent = hidden @ Wq_down
    gemm_f16_pipe<<<dim3(12, 32), 256, GEMM_SMEM_BYTES>>>(hidh, w1h, qlat, TOK, 1536, 2048);
    // 2. kvdr = hidden @ Wkv_down
    gemm_f16_pipe<<<dim3(5, 32), 256, GEMM_SMEM_BYTES>>>(hidh, w2h, kvdr, TOK, 576, 2048);
    // 3. rmsnorm q latent -> fp16
    rmsnorm_h_kernel<<<TOK, 256>>>(qlat, qlath, 1536);
    // 4. kv latent rmsnorm (-> fp16) + k_rope rope
    kvprep_kernel<<<TOK, 256>>>(kvdr, cosb, sinb, kvlath, krope);
    // 5. q raw = qlat @ Wq_up
    gemm_f16_pipe<<<dim3(24, 32), 256, GEMM_SMEM_BYTES>>>(qlath, w3h, qraw, TOK, 3072, 1536);
    // 6. kv = kvlat @ Wkv_up
    gemm_f16_pipe<<<dim3(32, 32), 256, GEMM_SMEM_BYTES>>>(kvlath, w4h, kv, TOK, 4096, 512);
    // 7. build q
    buildq_kernel<<<TOK, 256>>>(qraw, cosb, sinb, q);
    // 8. build k, v
    buildkv_kernel<<<TOK, 256>>>(kv, krope, k, v);
    // 9. fp16 tensor-core flash attention (-> fp16 out)
    attn_h_kernel<<<dim3(SEQ / 64, 2 * NH), 256, ATTN_SMEM_BYTES>>>(q, k, v, attnh);
    // 10. out = attn @ Wo
    gemm_f16_pipe<<<dim3(16, 32), 256, GEMM_SMEM_BYTES>>>(attnh, w5h, out, TOK, 2048, 2048);
}